// round 2
// baseline (speedup 1.0000x reference)
#include <cuda_runtime.h>

// pred:  (64, 512, 512) fp32   -> d_in[0]
// label: (64, 1, 512, 512) fp32 -> d_in[1]  (same linear layout per batch)
// out:   scalar fp32

#define BATCHES   64
#define N_ELEM    (512 * 512)          // per batch
#define N_F4      (N_ELEM / 4)         // 65536 float4 per batch
#define BPB       16                   // blocks per batch
#define TPB       256
#define NBLK      (BATCHES * BPB)      // 1024
#define F4_PER_SUB (N_F4 / BPB)        // 4096
#define ITERS     (F4_PER_SUB / TPB)   // 16

__device__ double g_mse [NBLK];
__device__ float  g_pval[NBLK];
__device__ int    g_pidx[NBLK];
__device__ float  g_lval[NBLK];
__device__ int    g_lidx[NBLK];

__global__ void __launch_bounds__(TPB) pass1(const float4* __restrict__ pred,
                                             const float4* __restrict__ label)
{
    const int blk = blockIdx.x;        // 0..1023
    const int b   = blk >> 4;          // batch
    const int sub = blk & 15;          // chunk within batch (ascending index ranges)
    const int t   = threadIdx.x;
    const size_t base = (size_t)b * N_F4;

    float pv = -3.402823466e38f; int pi = 0;
    float lv = -3.402823466e38f; int li = 0;
    float mse = 0.0f;

    #pragma unroll
    for (int k = 0; k < ITERS; k++) {
        const int f4 = sub * F4_PER_SUB + k * TPB + t;  // ascending in k per thread
        const float4 p = pred [base + f4];
        const float4 l = label[base + f4];
        const int e = f4 * 4;
        // strict > keeps the FIRST max (indices ascend within this thread's walk)
        if (p.x > pv) { pv = p.x; pi = e;     }
        if (p.y > pv) { pv = p.y; pi = e + 1; }
        if (p.z > pv) { pv = p.z; pi = e + 2; }
        if (p.w > pv) { pv = p.w; pi = e + 3; }
        if (l.x > lv) { lv = l.x; li = e;     }
        if (l.y > lv) { lv = l.y; li = e + 1; }
        if (l.z > lv) { lv = l.z; li = e + 2; }
        if (l.w > lv) { lv = l.w; li = e + 3; }
        const float dx = p.x - l.x;
        const float dy = p.y - l.y;
        const float dz = p.z - l.z;
        const float dw = p.w - l.w;
        mse += dx * dx + dy * dy + dz * dz + dw * dw;
    }

    __shared__ float  sPv[TPB]; __shared__ int sPi[TPB];
    __shared__ float  sLv[TPB]; __shared__ int sLi[TPB];
    __shared__ double sM [TPB];
    sPv[t] = pv; sPi[t] = pi;
    sLv[t] = lv; sLi[t] = li;
    sM[t]  = (double)mse;
    __syncthreads();

    for (int s = TPB / 2; s > 0; s >>= 1) {
        if (t < s) {
            if (sPv[t+s] > sPv[t] || (sPv[t+s] == sPv[t] && sPi[t+s] < sPi[t])) {
                sPv[t] = sPv[t+s]; sPi[t] = sPi[t+s];
            }
            if (sLv[t+s] > sLv[t] || (sLv[t+s] == sLv[t] && sLi[t+s] < sLi[t])) {
                sLv[t] = sLv[t+s]; sLi[t] = sLi[t+s];
            }
            sM[t] += sM[t+s];
        }
        __syncthreads();
    }

    if (t == 0) {
        g_mse [blk] = sM[0];
        g_pval[blk] = sPv[0]; g_pidx[blk] = sPi[0];
        g_lval[blk] = sLv[0]; g_lidx[blk] = sLi[0];
    }
}

__global__ void __launch_bounds__(1024) pass2(float* __restrict__ out)
{
    const int t = threadIdx.x;
    __shared__ double sM[1024];
    __shared__ double sIdx[64];

    sM[t] = g_mse[t];

    if (t < BATCHES) {
        float pv = -3.402823466e38f; int pi = 0;
        float lv = -3.402823466e38f; int li = 0;
        #pragma unroll
        for (int p = 0; p < BPB; p++) {
            const int j = t * BPB + p;   // chunks in ascending index order
            float v = g_pval[j]; int i = g_pidx[j];
            if (v > pv || (v == pv && i < pi)) { pv = v; pi = i; }
            v = g_lval[j]; i = g_lidx[j];
            if (v > lv || (v == lv && i < li)) { lv = v; li = i; }
        }
        const float rp = (float)(pi >> 9), cp = (float)(pi & 511);
        const float rl = (float)(li >> 9), cl = (float)(li & 511);
        const float dr = rp - rl, dc = cp - cl;
        sIdx[t] = (double)(dr * dr) + (double)(dc * dc);
    }
    __syncthreads();

    for (int s = 512; s > 0; s >>= 1) {
        if (t < s) sM[t] += sM[t + s];
        __syncthreads();
    }
    for (int s = 32; s > 0; s >>= 1) {
        if (t < s) sIdx[t] += sIdx[t + s];
        __syncthreads();
    }

    if (t == 0) {
        const double mse = sM[0];
        const double il  = sIdx[0];
        const double alpha = (il != 0.0) ? (mse / il) : 1.0;
        const double loss  = (mse + 0.25 * alpha * il) / (double)BATCHES;
        out[0] = (float)loss;
    }
}

extern "C" void kernel_launch(void* const* d_in, const int* in_sizes, int n_in,
                              void* d_out, int out_size)
{
    (void)in_sizes; (void)n_in; (void)out_size;
    const float4* pred  = (const float4*)d_in[0];
    const float4* label = (const float4*)d_in[1];
    float* out = (float*)d_out;

    pass1<<<NBLK, TPB>>>(pred, label);
    pass2<<<1, 1024>>>(out);
}

// round 3
// speedup vs baseline: 1.3902x; 1.3902x over previous
#include <cuda_runtime.h>

// pred:  (64, 512, 512) fp32   -> d_in[0]
// label: (64, 1, 512, 512) fp32 -> d_in[1]
// out:   scalar fp32
//
// Single fused kernel: 1024 streaming blocks produce per-chunk partials
// (MSE sum, first-index argmax for pred/label). The last block to finish
// (atomic ticket) reduces the 1024 partials from L2 and writes the scalar,
// then resets the ticket so graph replays are deterministic.

#define BATCHES   64
#define N_ELEM    (512 * 512)
#define N_F4      (N_ELEM / 4)         // 65536 float4 per batch
#define BPB       16                   // chunks (blocks) per batch
#define TPB       256
#define NBLK      (BATCHES * BPB)      // 1024
#define F4_PER_SUB (N_F4 / BPB)        // 4096
#define ITERS     (F4_PER_SUB / TPB)   // 16

__device__ double g_mse [NBLK];
__device__ float  g_pval[NBLK];
__device__ int    g_pidx[NBLK];
__device__ float  g_lval[NBLK];
__device__ int    g_lidx[NBLK];
__device__ int    g_ticket = 0;

__global__ void __launch_bounds__(TPB) fused(const float4* __restrict__ pred,
                                             const float4* __restrict__ label,
                                             float* __restrict__ out)
{
    const int blk = blockIdx.x;        // 0..1023
    const int b   = blk >> 4;          // batch
    const int sub = blk & 15;          // chunk within batch (ascending index ranges)
    const int t   = threadIdx.x;
    const size_t base = (size_t)b * N_F4;

    float pv = -3.402823466e38f; int pi = 0;
    float lv = -3.402823466e38f; int li = 0;
    float mse = 0.0f;

    #pragma unroll
    for (int k = 0; k < ITERS; k++) {
        const int f4 = sub * F4_PER_SUB + k * TPB + t;  // ascending in k per thread
        const float4 p = pred [base + f4];
        const float4 l = label[base + f4];
        const int e = f4 * 4;
        // strict > keeps the FIRST max (indices ascend within this thread's walk)
        if (p.x > pv) { pv = p.x; pi = e;     }
        if (p.y > pv) { pv = p.y; pi = e + 1; }
        if (p.z > pv) { pv = p.z; pi = e + 2; }
        if (p.w > pv) { pv = p.w; pi = e + 3; }
        if (l.x > lv) { lv = l.x; li = e;     }
        if (l.y > lv) { lv = l.y; li = e + 1; }
        if (l.z > lv) { lv = l.z; li = e + 2; }
        if (l.w > lv) { lv = l.w; li = e + 3; }
        const float dx = p.x - l.x;
        const float dy = p.y - l.y;
        const float dz = p.z - l.z;
        const float dw = p.w - l.w;
        mse += dx * dx + dy * dy + dz * dz + dw * dw;
    }

    __shared__ float  sPv[TPB]; __shared__ int sPi[TPB];
    __shared__ float  sLv[TPB]; __shared__ int sLi[TPB];
    __shared__ double sM [TPB];
    sPv[t] = pv; sPi[t] = pi;
    sLv[t] = lv; sLi[t] = li;
    sM[t]  = (double)mse;
    __syncthreads();

    for (int s = TPB / 2; s > 0; s >>= 1) {
        if (t < s) {
            if (sPv[t+s] > sPv[t] || (sPv[t+s] == sPv[t] && sPi[t+s] < sPi[t])) {
                sPv[t] = sPv[t+s]; sPi[t] = sPi[t+s];
            }
            if (sLv[t+s] > sLv[t] || (sLv[t+s] == sLv[t] && sLi[t+s] < sLi[t])) {
                sLv[t] = sLv[t+s]; sLi[t] = sLi[t+s];
            }
            sM[t] += sM[t+s];
        }
        __syncthreads();
    }

    __shared__ bool isLast;
    if (t == 0) {
        g_mse [blk] = sM[0];
        g_pval[blk] = sPv[0]; g_pidx[blk] = sPi[0];
        g_lval[blk] = sLv[0]; g_lidx[blk] = sLi[0];
        __threadfence();
        const int ticket = atomicAdd(&g_ticket, 1);
        isLast = (ticket == NBLK - 1);
    }
    __syncthreads();
    if (!isLast) return;

    // ---- final reduction in the last-finishing block ----
    __shared__ double fM[TPB];
    __shared__ double fIdx[BATCHES];

    // MSE total: each thread sums 4 consecutive partials (fixed order)
    {
        double s0 = 0.0;
        #pragma unroll
        for (int j = 0; j < 4; j++) s0 += g_mse[t * 4 + j];
        fM[t] = s0;
    }

    // Per-batch argmax merge: thread t < 64 owns batch t
    if (t < BATCHES) {
        float ppv = -3.402823466e38f; int ppi = 0;
        float llv = -3.402823466e38f; int lli = 0;
        #pragma unroll
        for (int p = 0; p < BPB; p++) {
            const int j = t * BPB + p;   // chunks in ascending index order
            float v = g_pval[j]; int i = g_pidx[j];
            if (v > ppv || (v == ppv && i < ppi)) { ppv = v; ppi = i; }
            v = g_lval[j]; i = g_lidx[j];
            if (v > llv || (v == llv && i < lli)) { llv = v; lli = i; }
        }
        const float rp = (float)(ppi >> 9), cp = (float)(ppi & 511);
        const float rl = (float)(lli >> 9), cl = (float)(lli & 511);
        const float dr = rp - rl, dc = cp - cl;
        fIdx[t] = (double)(dr * dr) + (double)(dc * dc);
    }
    __syncthreads();

    for (int s = TPB / 2; s > 0; s >>= 1) {
        if (t < s) fM[t] += fM[t + s];
        __syncthreads();
    }
    for (int s = BATCHES / 2; s > 0; s >>= 1) {
        if (t < s) fIdx[t] += fIdx[t + s];
        __syncthreads();
    }

    if (t == 0) {
        const double mseT = fM[0];
        const double il   = fIdx[0];
        const double alpha = (il != 0.0) ? (mseT / il) : 1.0;
        const double loss  = (mseT + 0.25 * alpha * il) / (double)BATCHES;
        out[0] = (float)loss;
        g_ticket = 0;   // reset for next (deterministic) replay
    }
}

extern "C" void kernel_launch(void* const* d_in, const int* in_sizes, int n_in,
                              void* d_out, int out_size)
{
    (void)in_sizes; (void)n_in; (void)out_size;
    const float4* pred  = (const float4*)d_in[0];
    const float4* label = (const float4*)d_in[1];
    float* out = (float*)d_out;

    fused<<<NBLK, TPB>>>(pred, label, out);
}